// round 13
// baseline (speedup 1.0000x reference)
#include <cuda_runtime.h>

#define NN 10000
#define NE 160000
#define CAP 96

#define SILU_C_F   1.6765867f
#define INV_S8     0.35355339059327373f
#define INV_S32    0.17677669529663687f
#define INV_S96    0.10206207261596575f
#define INV_S128   0.08838834764831845f
#define INV_S3     0.57735026918962576f
#define S3_DIV_S5  0.77459666924148338f   // sqrt(3/5)
#define IS2        0.70710678118654752f   // 1/sqrt(2)
#define IS6        0.40824829046386302f   // 1/sqrt(6)
#define C_S        0.38268343236508977f   // sin(pi/8)
#define C_X        0.92387953251128676f   // cos(pi/8)

// scratch
__device__ float g_y[NN * 160];
__device__ float g_s[NN * 160];       // self-connection, C_S pre-folded
__device__ float g_w[NE * 320];       // per-edge TP weights (GEMM output)
__device__ float g_agg[NN * 960];     // gathered accumulators [m(96)|m1T(384)|m2T(480)]
__device__ int   g_fill[NN];          // bucket fill counts (== degree); reset by k_gather
__device__ int   g_perm[NN * CAP];    // bucket CSR: edges of node n at [n*CAP, n*CAP+deg)

__device__ __forceinline__ unsigned long long pack2(float x) {
    unsigned long long r; asm("mov.b64 %0, {%1, %1};" : "=l"(r) : "f"(x)); return r;
}
__device__ __forceinline__ void fma2(unsigned long long& d, unsigned long long a, unsigned long long b) {
    asm("fma.rn.f32x2 %0, %1, %2, %0;" : "+l"(d) : "l"(a), "l"(b));
}
__device__ __forceinline__ float2 unpack2(unsigned long long v) {
    float2 f; asm("mov.b64 {%0, %1}, %2;" : "=f"(f.x), "=f"(f.y) : "l"(v)); return f;
}

// ---------------- bucket CSR build (replaces zero/hist/scan/fill) ----------------
__global__ void k_bucket(const int* __restrict__ edge_dst) {
    int e = blockIdx.x * blockDim.x + threadIdx.x;
    if (e < NE) {
        int d = __ldg(&edge_dst[e]);
        int p = atomicAdd(&g_fill[d], 1);
        g_perm[d * CAP + p] = e;
    }
}

// ---------------- node pre-linear: 16-node tile, col-owner, coalesced weights ----------------
__global__ __launch_bounds__(160) void k_node(
    const float* __restrict__ node_input, const float* __restrict__ node_attr,
    const float* __restrict__ lin1_w0, const float* __restrict__ sc_w0,
    const float* __restrict__ lin1_w1, const float* __restrict__ sc_w1)
{
    __shared__ float xs[16][160];
    __shared__ float natt[16];
    int n0 = blockIdx.x * 16, t = threadIdx.x;
    for (int idx = t; idx < 16 * 160; idx += 160) {
        int nn = idx / 160, col = idx - nn * 160;
        xs[nn][col] = node_input[(n0 + nn) * 160 + col];
    }
    if (t < 16) natt[t] = node_attr[n0 + t];
    __syncthreads();

    float accy[16], accs[16];
    #pragma unroll
    for (int nn = 0; nn < 16; nn++) { accy[nn] = 0.f; accs[nn] = 0.f; }

    if (t < 64) {
        #pragma unroll 1
        for (int uc = 0; uc < 64; uc += 16) {
            float wl[16], ws[16];
            #pragma unroll
            for (int q = 0; q < 16; q++) {
                wl[q] = __ldg(&lin1_w0[(uc + q) * 64 + t]);
                ws[q] = __ldg(&sc_w0[(uc + q) * 64 + t]);
            }
            #pragma unroll
            for (int nn = 0; nn < 16; nn++) {
                #pragma unroll
                for (int q = 0; q < 16; q += 4) {
                    float4 xv = *reinterpret_cast<const float4*>(&xs[nn][uc + q]);
                    accy[nn] = fmaf(xv.x, wl[q], fmaf(xv.y, wl[q+1], fmaf(xv.z, wl[q+2], fmaf(xv.w, wl[q+3], accy[nn]))));
                    accs[nn] = fmaf(xv.x, ws[q], fmaf(xv.y, ws[q+1], fmaf(xv.z, ws[q+2], fmaf(xv.w, ws[q+3], accs[nn]))));
                }
            }
        }
        #pragma unroll
        for (int nn = 0; nn < 16; nn++) {
            float a = natt[nn];
            g_y[(n0 + nn) * 160 + t] = accy[nn] * a * 0.125f;
            g_s[(n0 + nn) * 160 + t] = accs[nn] * a * (0.125f * C_S);
        }
    } else {
        int j = t - 64, v = j / 3, i = j - 3 * v;
        #pragma unroll 1
        for (int uc = 0; uc < 32; uc += 16) {
            float wl[16], ws[16];
            #pragma unroll
            for (int q = 0; q < 16; q++) {
                wl[q] = __ldg(&lin1_w1[(uc + q) * 32 + v]);
                ws[q] = __ldg(&sc_w1[(uc + q) * 32 + v]);
            }
            #pragma unroll
            for (int nn = 0; nn < 16; nn++) {
                #pragma unroll
                for (int q = 0; q < 16; q++) {
                    float xv = xs[nn][64 + (uc + q) * 3 + i];
                    accy[nn] = fmaf(xv, wl[q], accy[nn]);
                    accs[nn] = fmaf(xv, ws[q], accs[nn]);
                }
            }
        }
        #pragma unroll
        for (int nn = 0; nn < 16; nn++) {
            float a = natt[nn];
            g_y[(n0 + nn) * 160 + t] = accy[nn] * a * INV_S32;
            g_s[(n0 + nn) * 160 + t] = accs[nn] * a * (INV_S32 * C_S);
        }
    }
}

// ---------------- GEMM: W[e][c] = h(e) . fc_w1[:,c]; 4 cols x 8 edges per thread ----------------
#define GE 16
__global__ __launch_bounds__(160) void k_gemm(
    const float* __restrict__ ele, const float* __restrict__ fc_w0,
    const float* __restrict__ fc_w1)
{
    __shared__ float s_el[GE * 8];
    __shared__ float s_w0[512];
    __shared__ float sHT[64 * GE];   // sHT[k*16 + e]
    int t = threadIdx.x;
    int eb = blockIdx.x * GE;

    if (t < GE * 8) s_el[t] = ele[eb * 8 + t];
    for (int i = t; i < 512; i += 160) s_w0[i] = fc_w0[i];
    __syncthreads();

    if (t < 128) {
        int c = t >> 1, e0h = (t & 1) * 8;
        #pragma unroll
        for (int j = 0; j < 8; j++) {
            int e = e0h + j;
            float z = 0.f;
            #pragma unroll
            for (int k = 0; k < 8; k++) z = fmaf(s_el[e * 8 + k], s_w0[k * 64 + c], z);
            z *= INV_S8;
            float sg = __fdividef(1.f, 1.f + __expf(-z));
            sHT[c * GE + e] = z * sg * (SILU_C_F * 0.03125f);
        }
    }
    __syncthreads();

    int cq = t % 80;
    int eq = t / 80;
    int c0 = cq * 4;
    int e0 = eq * 8;

    unsigned long long acc[4][4];
    #pragma unroll
    for (int j = 0; j < 4; j++)
        #pragma unroll
        for (int p = 0; p < 4; p++) acc[j][p] = 0ULL;

    #pragma unroll 4
    for (int k = 0; k < 64; k++) {
        float4 wv = __ldg(reinterpret_cast<const float4*>(&fc_w1[k * 320 + c0]));
        unsigned long long w0 = pack2(wv.x), w1 = pack2(wv.y), w2 = pack2(wv.z), w3 = pack2(wv.w);
        const ulonglong2* hp = reinterpret_cast<const ulonglong2*>(&sHT[k * GE + e0]);
        ulonglong2 ha = hp[0];
        ulonglong2 hb = hp[1];
        fma2(acc[0][0], ha.x, w0); fma2(acc[0][1], ha.y, w0); fma2(acc[0][2], hb.x, w0); fma2(acc[0][3], hb.y, w0);
        fma2(acc[1][0], ha.x, w1); fma2(acc[1][1], ha.y, w1); fma2(acc[1][2], hb.x, w1); fma2(acc[1][3], hb.y, w1);
        fma2(acc[2][0], ha.x, w2); fma2(acc[2][1], ha.y, w2); fma2(acc[2][2], hb.x, w2); fma2(acc[2][3], hb.y, w2);
        fma2(acc[3][0], ha.x, w3); fma2(acc[3][1], ha.y, w3); fma2(acc[3][2], hb.x, w3); fma2(acc[3][3], hb.y, w3);
    }

    #pragma unroll
    for (int p = 0; p < 4; p++) {
        float2 v0 = unpack2(acc[0][p]), v1 = unpack2(acc[1][p]);
        float2 v2 = unpack2(acc[2][p]), v3 = unpack2(acc[3][p]);
        float4 lo = make_float4(v0.x, v1.x, v2.x, v3.x);
        float4 hi = make_float4(v0.y, v1.y, v2.y, v3.y);
        *reinterpret_cast<float4*>(&g_w[(eb + e0 + 2 * p) * 320 + c0]) = lo;
        *reinterpret_cast<float4*>(&g_w[(eb + e0 + 2 * p + 1) * 320 + c0]) = hi;
    }
}

// ---------------- gather v4: bucket CSR, single <=96-edge pass, batched-MLP loads ----------------
// thread t ownership (verified):
//   [0,64): k0  | [64,128): k2  | [128,192): k5 | [192,224): k3
//   [224,256): k1 | [256,288): k6 | [288,320): k4
__global__ __launch_bounds__(320) void k_gather(
    const float* __restrict__ edge_attr, const int* __restrict__ edge_src)
{
    __shared__ float mall[960];      // [m(96) | m1T(384) | m2T(480)]
    __shared__ int sed[CAP];
    __shared__ int ssrc[CAP];
    __shared__ float sea[CAP][10];   // staged edge_attr (9 used, pad to 10)
    __shared__ int sdeg;
    float* m   = mall;
    float* m1T = mall + 96;
    float* m2T = mall + 480;

    int n = blockIdx.x, t = threadIdx.x;
    if (t == 0) { sdeg = g_fill[n]; g_fill[n] = 0; }   // read degree + reset for next replay
    __syncthreads();
    int deg = sdeg;
    float acc0 = 0.f, acc1 = 0.f, acc2 = 0.f, acc3 = 0.f, acc4 = 0.f;

    int eabase;
    if      (t < 64)  eabase = 0;
    else if (t < 128) eabase = 1;
    else if (t < 192) eabase = 4;
    else if (t < 224) eabase = 0;
    else if (t < 288) eabase = 1;
    else              eabase = 4;

    if (t < deg) {
        int e = __ldg(&g_perm[n * CAP + t]);
        sed[t] = e;
        ssrc[t] = __ldg(&edge_src[e]);
    }
    __syncthreads();
    for (int idx = t; idx < deg * 9; idx += 320) {
        int e = idx / 9, j = idx - 9 * e;
        sea[e][j] = __ldg(&edge_attr[sed[e] * 9 + j]);
    }
    __syncthreads();

    for (int cb = 0; cb < deg; cb += 4) {
        // ---- batch loads (4 edges, independent -> MLP) ----
        float wv[4], ya[4], yb[4], yc[4];
        #pragma unroll
        for (int j = 0; j < 4; j++) {
            int ii = cb + j;
            bool act = ii < deg;
            int e = act ? sed[ii] : sed[0];
            int s = act ? ssrc[ii] : ssrc[0];
            wv[j] = __ldg(&g_w[e * 320 + t]);
            if (t < 192) {
                ya[j] = __ldg(&g_y[s * 160 + (t & 63)]);
                yb[j] = 0.f; yc[j] = 0.f;
            } else {
                const float* yp = &g_y[s * 160 + 64 + 3 * ((t - 192) & 31)];
                ya[j] = __ldg(yp); yb[j] = __ldg(yp + 1); yc[j] = __ldg(yp + 2);
            }
            if (!act) wv[j] = 0.f;   // wv=0 nullifies every path's contribution
        }
        // ---- consume batch ----
        #pragma unroll
        for (int j = 0; j < 4; j++) {
            int ii = cb + j; if (ii >= deg) ii = deg - 1;
            const float* er = &sea[ii][eabase];
            float w = wv[j], y0 = ya[j], y1 = yb[j], y2 = yc[j];
            if (t < 64) {
                acc0 = fmaf(y0 * er[0], w, acc0);
            } else if (t < 128) {
                float b = y0 * w;
                acc0 = fmaf(b, er[0], acc0); acc1 = fmaf(b, er[1], acc1); acc2 = fmaf(b, er[2], acc2);
            } else if (t < 192) {
                float b = y0 * w;
                acc0 = fmaf(b, er[0], acc0); acc1 = fmaf(b, er[1], acc1); acc2 = fmaf(b, er[2], acc2);
                acc3 = fmaf(b, er[3], acc3); acc4 = fmaf(b, er[4], acc4);
            } else if (t < 224) {
                float b = er[0] * w;
                acc0 = fmaf(b, y0, acc0); acc1 = fmaf(b, y1, acc1); acc2 = fmaf(b, y2, acc2);
            } else if (t < 256) {
                acc0 = fmaf(INV_S3 * w, fmaf(y0, er[0], fmaf(y1, er[1], y2 * er[2])), acc0);
            } else if (t < 288) {
                float s = -w;
                acc0 = fmaf(s, (y2 * er[0] + y0 * er[2]) * IS2, acc0);
                acc1 = fmaf(s, (y0 * er[1] + y1 * er[0]) * IS2, acc1);
                acc2 = fmaf(s, (-y0 * er[0] + 2.f * y1 * er[1] - y2 * er[2]) * IS6, acc2);
                acc3 = fmaf(s, (y1 * er[2] + y2 * er[1]) * IS2, acc3);
                acc4 = fmaf(s, (-y0 * er[0] + y2 * er[2]) * IS2, acc4);
            } else {
                float p0 = er[0], p1 = er[1], p2 = er[2], p3 = er[3], p4 = er[4];
                float Myy = -p2 * IS6 - p4 * IS2;
                float Mzz =  2.f * p2 * IS6;
                float Mxx = -p2 * IS6 + p4 * IS2;
                float Myz =  p1 * IS2;
                float Myx =  p0 * IS2;
                float Mzx =  p3 * IS2;
                float s = S3_DIV_S5 * w;
                acc0 = fmaf(s, fmaf(Myy, y0, fmaf(Myz, y1, Myx * y2)), acc0);
                acc1 = fmaf(s, fmaf(Myz, y0, fmaf(Mzz, y1, Mzx * y2)), acc1);
                acc2 = fmaf(s, fmaf(Myx, y0, fmaf(Mzx, y1, Mxx * y2)), acc2);
            }
        }
    }

    // stage accumulators into lin2-friendly smem layouts
    if (t < 64) {
        m[t] = acc0;
    } else if (t < 128) {
        int u = t - 64;
        m1T[u] = acc0; m1T[128 + u] = acc1; m1T[256 + u] = acc2;
    } else if (t < 192) {
        int u = t - 128;
        m2T[u] = acc0; m2T[96 + u] = acc1; m2T[192 + u] = acc2;
        m2T[288 + u] = acc3; m2T[384 + u] = acc4;
    } else if (t < 224) {
        int v = t - 192 + 64;
        m1T[v] = acc0; m1T[128 + v] = acc1; m1T[256 + v] = acc2;
    } else if (t < 256) {
        m[64 + (t - 224)] = acc0;
    } else if (t < 288) {
        int v = t - 256 + 64;
        m2T[v] = acc0; m2T[96 + v] = acc1; m2T[192 + v] = acc2;
        m2T[288 + v] = acc3; m2T[384 + v] = acc4;
    } else {
        int v = t - 288 + 96;
        m1T[v] = acc0; m1T[128 + v] = acc1; m1T[256 + v] = acc2;
    }
    __syncthreads();

    for (int idx = t; idx < 960; idx += 320)
        g_agg[n * 960 + idx] = mall[idx];
}

// ---------------- output: lin2 + combine; 16-node tile, col-owner, coalesced weights ----------------
__global__ __launch_bounds__(320) void k_out(
    const float* __restrict__ node_attr,
    const float* __restrict__ lin2_w0, const float* __restrict__ lin2_w1,
    const float* __restrict__ lin2_w2, float* __restrict__ out)
{
    extern __shared__ float sag[];   // [16][960]
    __shared__ float natt[16];
    int n0 = blockIdx.x * 16, t = threadIdx.x;
    for (int idx = t; idx < 16 * 960; idx += 320)
        sag[idx] = g_agg[n0 * 960 + idx];
    if (t < 16) natt[t] = node_attr[n0 + t];
    __syncthreads();

    float acc[16];
    #pragma unroll
    for (int nn = 0; nn < 16; nn++) acc[nn] = 0.f;

    if (t < 64) {
        #pragma unroll 1
        for (int pc = 0; pc < 96; pc += 16) {
            float w[16];
            #pragma unroll
            for (int q = 0; q < 16; q++) w[q] = __ldg(&lin2_w0[(pc + q) * 64 + t]);
            #pragma unroll
            for (int nn = 0; nn < 16; nn++) {
                const float* mp = &sag[nn * 960 + pc];
                #pragma unroll
                for (int q = 0; q < 16; q += 4) {
                    float4 mv = *reinterpret_cast<const float4*>(mp + q);
                    acc[nn] = fmaf(mv.x, w[q], fmaf(mv.y, w[q+1], fmaf(mv.z, w[q+2], fmaf(mv.w, w[q+3], acc[nn]))));
                }
            }
        }
        #pragma unroll
        for (int nn = 0; nn < 16; nn++) {
            int n = n0 + nn;
            out[n * 320 + t] = __ldg(&g_s[n * 160 + t]) + acc[nn] * natt[nn] * (C_X * INV_S96);
        }
    } else if (t < 160) {
        int j = t - 64, v = j / 3, i = j - 3 * v;
        #pragma unroll 1
        for (int pc = 0; pc < 128; pc += 16) {
            float w[16];
            #pragma unroll
            for (int q = 0; q < 16; q++) w[q] = __ldg(&lin2_w1[(pc + q) * 32 + v]);
            #pragma unroll
            for (int nn = 0; nn < 16; nn++) {
                const float* mp = &sag[nn * 960 + 96 + i * 128 + pc];
                #pragma unroll
                for (int q = 0; q < 16; q += 4) {
                    float4 mv = *reinterpret_cast<const float4*>(mp + q);
                    acc[nn] = fmaf(mv.x, w[q], fmaf(mv.y, w[q+1], fmaf(mv.z, w[q+2], fmaf(mv.w, w[q+3], acc[nn]))));
                }
            }
        }
        #pragma unroll
        for (int nn = 0; nn < 16; nn++) {
            int n = n0 + nn;
            out[n * 320 + t] = __ldg(&g_s[n * 160 + t]) + acc[nn] * natt[nn] * (C_X * INV_S128);
        }
    } else {
        int j = t - 160, v = j / 5, i = j - 5 * v;
        #pragma unroll 1
        for (int pc = 0; pc < 96; pc += 16) {
            float w[16];
            #pragma unroll
            for (int q = 0; q < 16; q++) w[q] = __ldg(&lin2_w2[(pc + q) * 32 + v]);
            #pragma unroll
            for (int nn = 0; nn < 16; nn++) {
                const float* mp = &sag[nn * 960 + 480 + i * 96 + pc];
                #pragma unroll
                for (int q = 0; q < 16; q += 4) {
                    float4 mv = *reinterpret_cast<const float4*>(mp + q);
                    acc[nn] = fmaf(mv.x, w[q], fmaf(mv.y, w[q+1], fmaf(mv.z, w[q+2], fmaf(mv.w, w[q+3], acc[nn]))));
                }
            }
        }
        #pragma unroll
        for (int nn = 0; nn < 16; nn++) {
            int n = n0 + nn;
            out[n * 320 + t] = acc[nn] * natt[nn] * INV_S96;
        }
    }
}

extern "C" void kernel_launch(void* const* d_in, const int* in_sizes, int n_in,
                              void* d_out, int out_size)
{
    const float* node_input = (const float*)d_in[0];
    const float* node_attr  = (const float*)d_in[1];
    const int*   edge_src   = (const int*)  d_in[2];
    const int*   edge_dst   = (const int*)  d_in[3];
    const float* edge_attr  = (const float*)d_in[4];
    const float* ele        = (const float*)d_in[5];
    const float* sc_w0      = (const float*)d_in[6];
    const float* sc_w1      = (const float*)d_in[7];
    const float* lin1_w0    = (const float*)d_in[8];
    const float* lin1_w1    = (const float*)d_in[9];
    const float* fc_w0      = (const float*)d_in[10];
    const float* fc_w1      = (const float*)d_in[11];
    const float* lin2_w0    = (const float*)d_in[12];
    const float* lin2_w1    = (const float*)d_in[13];
    const float* lin2_w2    = (const float*)d_in[14];
    float* out = (float*)d_out;

    static cudaStream_t s2 = nullptr;
    static cudaEvent_t evA = nullptr, evB = nullptr;
    if (s2 == nullptr) {
        cudaStreamCreateWithFlags(&s2, cudaStreamNonBlocking);
        cudaEventCreateWithFlags(&evA, cudaEventDisableTiming);
        cudaEventCreateWithFlags(&evB, cudaEventDisableTiming);
    }

    const int smem_out = 16 * 960 * 4;   // 60 KB
    cudaFuncSetAttribute(k_out, cudaFuncAttributeMaxDynamicSharedMemorySize, smem_out);

    // fork point at capture origin: gemm depends only on raw inputs
    cudaEventRecord(evA, 0);
    cudaStreamWaitEvent(s2, evA, 0);

    k_bucket<<<(NE + 255) / 256, 256>>>(edge_dst);                                   // idx 0
    k_node<<<NN / 16, 160>>>(node_input, node_attr, lin1_w0, sc_w0, lin1_w1, sc_w1); // idx 1
    k_gemm<<<NE / GE, 160, 0, s2>>>(ele, fc_w0, fc_w1);                              // idx 2 (concurrent)
    cudaEventRecord(evB, s2);
    cudaStreamWaitEvent(0, evB, 0);

    k_gather<<<NN, 320>>>(edge_attr, edge_src);                                      // idx 3 -> profiled
    k_out<<<NN / 16, 320, smem_out>>>(node_attr, lin2_w0, lin2_w1, lin2_w2, out);    // idx 4
}

// round 14
// speedup vs baseline: 1.1965x; 1.1965x over previous
#include <cuda_runtime.h>
#include <cstdint>

#define NN 10000
#define NE 160000
#define CAP 96
#define TE 16

#define SILU_C_F   1.6765867f
#define INV_S8     0.35355339059327373f
#define INV_S32    0.17677669529663687f
#define INV_S96    0.10206207261596575f
#define INV_S128   0.08838834764831845f
#define INV_S3     0.57735026918962576f
#define S3_DIV_S5  0.77459666924148338f   // sqrt(3/5)
#define IS2        0.70710678118654752f   // 1/sqrt(2)
#define IS6        0.40824829046386302f   // 1/sqrt(6)
#define C_S        0.38268343236508977f   // sin(pi/8)
#define C_X        0.92387953251128676f   // cos(pi/8)

// scratch
__device__ float g_y[NN * 160];
__device__ float g_s[NN * 160];       // self-connection, C_S pre-folded
__device__ float g_w[NE * 320];       // per-edge TP weights (GEMM output)
__device__ float g_agg[NN * 960];     // gathered accumulators [m(96)|m1T(384)|m2T(480)]
__device__ int   g_fill[NN];          // bucket fill counts (== degree); reset by k_gather
__device__ int   g_perm[NN * CAP];    // bucket CSR

__device__ __forceinline__ unsigned long long pack2(float x) {
    unsigned long long r; asm("mov.b64 %0, {%1, %1};" : "=l"(r) : "f"(x)); return r;
}
__device__ __forceinline__ void fma2(unsigned long long& d, unsigned long long a, unsigned long long b) {
    asm("fma.rn.f32x2 %0, %1, %2, %0;" : "+l"(d) : "l"(a), "l"(b));
}
__device__ __forceinline__ float2 unpack2(unsigned long long v) {
    float2 f; asm("mov.b64 {%0, %1}, %2;" : "=f"(f.x), "=f"(f.y) : "l"(v)); return f;
}
__device__ __forceinline__ void cpa16(uint32_t s, const void* g) {
    asm volatile("cp.async.cg.shared.global [%0], [%1], 16;" :: "r"(s), "l"(g) : "memory");
}
#define CPA_COMMIT() asm volatile("cp.async.commit_group;" ::: "memory")
#define CPA_WAIT0()  asm volatile("cp.async.wait_group 0;" ::: "memory")

// ---------------- bucket CSR build ----------------
__global__ void k_bucket(const int* __restrict__ edge_dst) {
    int e = blockIdx.x * blockDim.x + threadIdx.x;
    if (e < NE) {
        int d = __ldg(&edge_dst[e]);
        int p = atomicAdd(&g_fill[d], 1);
        g_perm[d * CAP + p] = e;
    }
}

// ---------------- node pre-linear: 16-node tile, col-owner, coalesced weights ----------------
__global__ __launch_bounds__(160) void k_node(
    const float* __restrict__ node_input, const float* __restrict__ node_attr,
    const float* __restrict__ lin1_w0, const float* __restrict__ sc_w0,
    const float* __restrict__ lin1_w1, const float* __restrict__ sc_w1)
{
    __shared__ float xs[16][160];
    __shared__ float natt[16];
    int n0 = blockIdx.x * 16, t = threadIdx.x;
    for (int idx = t; idx < 16 * 160; idx += 160) {
        int nn = idx / 160, col = idx - nn * 160;
        xs[nn][col] = node_input[(n0 + nn) * 160 + col];
    }
    if (t < 16) natt[t] = node_attr[n0 + t];
    __syncthreads();

    float accy[16], accs[16];
    #pragma unroll
    for (int nn = 0; nn < 16; nn++) { accy[nn] = 0.f; accs[nn] = 0.f; }

    if (t < 64) {
        #pragma unroll 1
        for (int uc = 0; uc < 64; uc += 16) {
            float wl[16], ws[16];
            #pragma unroll
            for (int q = 0; q < 16; q++) {
                wl[q] = __ldg(&lin1_w0[(uc + q) * 64 + t]);
                ws[q] = __ldg(&sc_w0[(uc + q) * 64 + t]);
            }
            #pragma unroll
            for (int nn = 0; nn < 16; nn++) {
                #pragma unroll
                for (int q = 0; q < 16; q += 4) {
                    float4 xv = *reinterpret_cast<const float4*>(&xs[nn][uc + q]);
                    accy[nn] = fmaf(xv.x, wl[q], fmaf(xv.y, wl[q+1], fmaf(xv.z, wl[q+2], fmaf(xv.w, wl[q+3], accy[nn]))));
                    accs[nn] = fmaf(xv.x, ws[q], fmaf(xv.y, ws[q+1], fmaf(xv.z, ws[q+2], fmaf(xv.w, ws[q+3], accs[nn]))));
                }
            }
        }
        #pragma unroll
        for (int nn = 0; nn < 16; nn++) {
            float a = natt[nn];
            g_y[(n0 + nn) * 160 + t] = accy[nn] * a * 0.125f;
            g_s[(n0 + nn) * 160 + t] = accs[nn] * a * (0.125f * C_S);
        }
    } else {
        int j = t - 64, v = j / 3, i = j - 3 * v;
        #pragma unroll 1
        for (int uc = 0; uc < 32; uc += 16) {
            float wl[16], ws[16];
            #pragma unroll
            for (int q = 0; q < 16; q++) {
                wl[q] = __ldg(&lin1_w1[(uc + q) * 32 + v]);
                ws[q] = __ldg(&sc_w1[(uc + q) * 32 + v]);
            }
            #pragma unroll
            for (int nn = 0; nn < 16; nn++) {
                #pragma unroll
                for (int q = 0; q < 16; q++) {
                    float xv = xs[nn][64 + (uc + q) * 3 + i];
                    accy[nn] = fmaf(xv, wl[q], accy[nn]);
                    accs[nn] = fmaf(xv, ws[q], accs[nn]);
                }
            }
        }
        #pragma unroll
        for (int nn = 0; nn < 16; nn++) {
            float a = natt[nn];
            g_y[(n0 + nn) * 160 + t] = accy[nn] * a * INV_S32;
            g_s[(n0 + nn) * 160 + t] = accs[nn] * a * (INV_S32 * C_S);
        }
    }
}

// ---------------- GEMM: W[e][c] = h(e) . fc_w1[:,c]; 4 cols x 8 edges per thread ----------------
#define GE 16
__global__ __launch_bounds__(160) void k_gemm(
    const float* __restrict__ ele, const float* __restrict__ fc_w0,
    const float* __restrict__ fc_w1)
{
    __shared__ float s_el[GE * 8];
    __shared__ float s_w0[512];
    __shared__ float sHT[64 * GE];   // sHT[k*16 + e]
    int t = threadIdx.x;
    int eb = blockIdx.x * GE;

    if (t < GE * 8) s_el[t] = ele[eb * 8 + t];
    for (int i = t; i < 512; i += 160) s_w0[i] = fc_w0[i];
    __syncthreads();

    if (t < 128) {
        int c = t >> 1, e0h = (t & 1) * 8;
        #pragma unroll
        for (int j = 0; j < 8; j++) {
            int e = e0h + j;
            float z = 0.f;
            #pragma unroll
            for (int k = 0; k < 8; k++) z = fmaf(s_el[e * 8 + k], s_w0[k * 64 + c], z);
            z *= INV_S8;
            float sg = __fdividef(1.f, 1.f + __expf(-z));
            sHT[c * GE + e] = z * sg * (SILU_C_F * 0.03125f);
        }
    }
    __syncthreads();

    int cq = t % 80;
    int eq = t / 80;
    int c0 = cq * 4;
    int e0 = eq * 8;

    unsigned long long acc[4][4];
    #pragma unroll
    for (int j = 0; j < 4; j++)
        #pragma unroll
        for (int p = 0; p < 4; p++) acc[j][p] = 0ULL;

    #pragma unroll 4
    for (int k = 0; k < 64; k++) {
        float4 wv = __ldg(reinterpret_cast<const float4*>(&fc_w1[k * 320 + c0]));
        unsigned long long w0 = pack2(wv.x), w1 = pack2(wv.y), w2 = pack2(wv.z), w3 = pack2(wv.w);
        const ulonglong2* hp = reinterpret_cast<const ulonglong2*>(&sHT[k * GE + e0]);
        ulonglong2 ha = hp[0];
        ulonglong2 hb = hp[1];
        fma2(acc[0][0], ha.x, w0); fma2(acc[0][1], ha.y, w0); fma2(acc[0][2], hb.x, w0); fma2(acc[0][3], hb.y, w0);
        fma2(acc[1][0], ha.x, w1); fma2(acc[1][1], ha.y, w1); fma2(acc[1][2], hb.x, w1); fma2(acc[1][3], hb.y, w1);
        fma2(acc[2][0], ha.x, w2); fma2(acc[2][1], ha.y, w2); fma2(acc[2][2], hb.x, w2); fma2(acc[2][3], hb.y, w2);
        fma2(acc[3][0], ha.x, w3); fma2(acc[3][1], ha.y, w3); fma2(acc[3][2], hb.x, w3); fma2(acc[3][3], hb.y, w3);
    }

    #pragma unroll
    for (int p = 0; p < 4; p++) {
        float2 v0 = unpack2(acc[0][p]), v1 = unpack2(acc[1][p]);
        float2 v2 = unpack2(acc[2][p]), v3 = unpack2(acc[3][p]);
        float4 lo = make_float4(v0.x, v1.x, v2.x, v3.x);
        float4 hi = make_float4(v0.y, v1.y, v2.y, v3.y);
        *reinterpret_cast<float4*>(&g_w[(eb + e0 + 2 * p) * 320 + c0]) = lo;
        *reinterpret_cast<float4*>(&g_w[(eb + e0 + 2 * p + 1) * 320 + c0]) = hi;
    }
}

// ---------------- gather v5: cp.async tile staging of W + y; pure smem consume ----------------
// thread t ownership (verified):
//   [0,64): k0  | [64,128): k2  | [128,192): k5 | [192,224): k3
//   [224,256): k1 | [256,288): k6 | [288,320): k4
__global__ __launch_bounds__(320) void k_gather(
    const float* __restrict__ edge_attr, const int* __restrict__ edge_src)
{
    __shared__ __align__(16) float sW[TE][320];   // 20 KB
    __shared__ __align__(16) float sY[TE][160];   // 10 KB
    __shared__ float mall[960];
    __shared__ float sea[CAP][12];
    __shared__ int sed[CAP];
    __shared__ int ssrc[CAP];
    __shared__ int sdeg;
    float* m   = mall;
    float* m1T = mall + 96;
    float* m2T = mall + 480;

    int n = blockIdx.x, t = threadIdx.x;
    if (t == 0) { sdeg = g_fill[n]; g_fill[n] = 0; }
    __syncthreads();
    int deg = sdeg;
    float acc0 = 0.f, acc1 = 0.f, acc2 = 0.f, acc3 = 0.f, acc4 = 0.f;

    int eabase;
    if      (t < 64)  eabase = 0;
    else if (t < 128) eabase = 1;
    else if (t < 192) eabase = 4;
    else if (t < 224) eabase = 0;
    else if (t < 288) eabase = 1;
    else              eabase = 4;

    if (t < deg) {
        int e = __ldg(&g_perm[n * CAP + t]);
        sed[t] = e;
        ssrc[t] = __ldg(&edge_src[e]);
    }
    __syncthreads();
    for (int idx = t; idx < deg * 9; idx += 320) {
        int e = idx / 9, j = idx - 9 * e;
        sea[e][j] = __ldg(&edge_attr[sed[e] * 9 + j]);
    }

    uint32_t sWb = (uint32_t)__cvta_generic_to_shared(&sW[0][0]);
    uint32_t sYb = (uint32_t)__cvta_generic_to_shared(&sY[0][0]);

    for (int tb = 0; tb < deg; tb += TE) {
        int nt = deg - tb; if (nt > TE) nt = TE;
        // stage W rows (80 x 16B) + y rows (40 x 16B) per edge via cp.async
        for (int idx = t; idx < nt * 120; idx += 320) {
            int j = idx / 120, q = idx - j * 120;
            if (q < 80) {
                cpa16(sWb + (uint32_t)(j * 320 + q * 4) * 4,
                      &g_w[(size_t)sed[tb + j] * 320 + q * 4]);
            } else {
                int r = q - 80;
                cpa16(sYb + (uint32_t)(j * 160 + r * 4) * 4,
                      &g_y[(size_t)ssrc[tb + j] * 160 + r * 4]);
            }
        }
        CPA_COMMIT();
        CPA_WAIT0();
        __syncthreads();

        #pragma unroll 4
        for (int j = 0; j < nt; j++) {
            float w = sW[j][t];
            float y0, y1 = 0.f, y2 = 0.f;
            if (t < 192) {
                y0 = sY[j][t & 63];
            } else {
                int v3 = 64 + 3 * ((t - 192) & 31);
                y0 = sY[j][v3]; y1 = sY[j][v3 + 1]; y2 = sY[j][v3 + 2];
            }
            const float* er = &sea[tb + j][eabase];
            if (t < 64) {
                acc0 = fmaf(y0 * er[0], w, acc0);
            } else if (t < 128) {
                float b = y0 * w;
                acc0 = fmaf(b, er[0], acc0); acc1 = fmaf(b, er[1], acc1); acc2 = fmaf(b, er[2], acc2);
            } else if (t < 192) {
                float b = y0 * w;
                acc0 = fmaf(b, er[0], acc0); acc1 = fmaf(b, er[1], acc1); acc2 = fmaf(b, er[2], acc2);
                acc3 = fmaf(b, er[3], acc3); acc4 = fmaf(b, er[4], acc4);
            } else if (t < 224) {
                float b = er[0] * w;
                acc0 = fmaf(b, y0, acc0); acc1 = fmaf(b, y1, acc1); acc2 = fmaf(b, y2, acc2);
            } else if (t < 256) {
                acc0 = fmaf(INV_S3 * w, fmaf(y0, er[0], fmaf(y1, er[1], y2 * er[2])), acc0);
            } else if (t < 288) {
                float s = -w;
                acc0 = fmaf(s, (y2 * er[0] + y0 * er[2]) * IS2, acc0);
                acc1 = fmaf(s, (y0 * er[1] + y1 * er[0]) * IS2, acc1);
                acc2 = fmaf(s, (-y0 * er[0] + 2.f * y1 * er[1] - y2 * er[2]) * IS6, acc2);
                acc3 = fmaf(s, (y1 * er[2] + y2 * er[1]) * IS2, acc3);
                acc4 = fmaf(s, (-y0 * er[0] + y2 * er[2]) * IS2, acc4);
            } else {
                float p0 = er[0], p1 = er[1], p2 = er[2], p3 = er[3], p4 = er[4];
                float Myy = -p2 * IS6 - p4 * IS2;
                float Mzz =  2.f * p2 * IS6;
                float Mxx = -p2 * IS6 + p4 * IS2;
                float Myz =  p1 * IS2;
                float Myx =  p0 * IS2;
                float Mzx =  p3 * IS2;
                float s = S3_DIV_S5 * w;
                acc0 = fmaf(s, fmaf(Myy, y0, fmaf(Myz, y1, Myx * y2)), acc0);
                acc1 = fmaf(s, fmaf(Myz, y0, fmaf(Mzz, y1, Mzx * y2)), acc1);
                acc2 = fmaf(s, fmaf(Myx, y0, fmaf(Mzx, y1, Mxx * y2)), acc2);
            }
        }
        __syncthreads();   // before buffer reuse
    }

    // stage accumulators into lin2-friendly smem layouts
    if (t < 64) {
        m[t] = acc0;
    } else if (t < 128) {
        int u = t - 64;
        m1T[u] = acc0; m1T[128 + u] = acc1; m1T[256 + u] = acc2;
    } else if (t < 192) {
        int u = t - 128;
        m2T[u] = acc0; m2T[96 + u] = acc1; m2T[192 + u] = acc2;
        m2T[288 + u] = acc3; m2T[384 + u] = acc4;
    } else if (t < 224) {
        int v = t - 192 + 64;
        m1T[v] = acc0; m1T[128 + v] = acc1; m1T[256 + v] = acc2;
    } else if (t < 256) {
        m[64 + (t - 224)] = acc0;
    } else if (t < 288) {
        int v = t - 256 + 64;
        m2T[v] = acc0; m2T[96 + v] = acc1; m2T[192 + v] = acc2;
        m2T[288 + v] = acc3; m2T[384 + v] = acc4;
    } else {
        int v = t - 288 + 96;
        m1T[v] = acc0; m1T[128 + v] = acc1; m1T[256 + v] = acc2;
    }
    __syncthreads();

    for (int idx = t; idx < 960; idx += 320)
        g_agg[n * 960 + idx] = mall[idx];
}

// ---------------- output: lin2 + combine; 16-node tile, col-owner, coalesced weights ----------------
__global__ __launch_bounds__(320) void k_out(
    const float* __restrict__ node_attr,
    const float* __restrict__ lin2_w0, const float* __restrict__ lin2_w1,
    const float* __restrict__ lin2_w2, float* __restrict__ out)
{
    extern __shared__ float sag[];   // [16][960]
    __shared__ float natt[16];
    int n0 = blockIdx.x * 16, t = threadIdx.x;
    for (int idx = t; idx < 16 * 960; idx += 320)
        sag[idx] = g_agg[n0 * 960 + idx];
    if (t < 16) natt[t] = node_attr[n0 + t];
    __syncthreads();

    float acc[16];
    #pragma unroll
    for (int nn = 0; nn < 16; nn++) acc[nn] = 0.f;

    if (t < 64) {
        #pragma unroll 1
        for (int pc = 0; pc < 96; pc += 16) {
            float w[16];
            #pragma unroll
            for (int q = 0; q < 16; q++) w[q] = __ldg(&lin2_w0[(pc + q) * 64 + t]);
            #pragma unroll
            for (int nn = 0; nn < 16; nn++) {
                const float* mp = &sag[nn * 960 + pc];
                #pragma unroll
                for (int q = 0; q < 16; q += 4) {
                    float4 mv = *reinterpret_cast<const float4*>(mp + q);
                    acc[nn] = fmaf(mv.x, w[q], fmaf(mv.y, w[q+1], fmaf(mv.z, w[q+2], fmaf(mv.w, w[q+3], acc[nn]))));
                }
            }
        }
        #pragma unroll
        for (int nn = 0; nn < 16; nn++) {
            int n = n0 + nn;
            out[n * 320 + t] = __ldg(&g_s[n * 160 + t]) + acc[nn] * natt[nn] * (C_X * INV_S96);
        }
    } else if (t < 160) {
        int j = t - 64, v = j / 3, i = j - 3 * v;
        #pragma unroll 1
        for (int pc = 0; pc < 128; pc += 16) {
            float w[16];
            #pragma unroll
            for (int q = 0; q < 16; q++) w[q] = __ldg(&lin2_w1[(pc + q) * 32 + v]);
            #pragma unroll
            for (int nn = 0; nn < 16; nn++) {
                const float* mp = &sag[nn * 960 + 96 + i * 128 + pc];
                #pragma unroll
                for (int q = 0; q < 16; q += 4) {
                    float4 mv = *reinterpret_cast<const float4*>(mp + q);
                    acc[nn] = fmaf(mv.x, w[q], fmaf(mv.y, w[q+1], fmaf(mv.z, w[q+2], fmaf(mv.w, w[q+3], acc[nn]))));
                }
            }
        }
        #pragma unroll
        for (int nn = 0; nn < 16; nn++) {
            int n = n0 + nn;
            out[n * 320 + t] = __ldg(&g_s[n * 160 + t]) + acc[nn] * natt[nn] * (C_X * INV_S128);
        }
    } else {
        int j = t - 160, v = j / 5, i = j - 5 * v;
        #pragma unroll 1
        for (int pc = 0; pc < 96; pc += 16) {
            float w[16];
            #pragma unroll
            for (int q = 0; q < 16; q++) w[q] = __ldg(&lin2_w2[(pc + q) * 32 + v]);
            #pragma unroll
            for (int nn = 0; nn < 16; nn++) {
                const float* mp = &sag[nn * 960 + 480 + i * 96 + pc];
                #pragma unroll
                for (int q = 0; q < 16; q += 4) {
                    float4 mv = *reinterpret_cast<const float4*>(mp + q);
                    acc[nn] = fmaf(mv.x, w[q], fmaf(mv.y, w[q+1], fmaf(mv.z, w[q+2], fmaf(mv.w, w[q+3], acc[nn]))));
                }
            }
        }
        #pragma unroll
        for (int nn = 0; nn < 16; nn++) {
            int n = n0 + nn;
            out[n * 320 + t] = acc[nn] * natt[nn] * INV_S96;
        }
    }
}

extern "C" void kernel_launch(void* const* d_in, const int* in_sizes, int n_in,
                              void* d_out, int out_size)
{
    const float* node_input = (const float*)d_in[0];
    const float* node_attr  = (const float*)d_in[1];
    const int*   edge_src   = (const int*)  d_in[2];
    const int*   edge_dst   = (const int*)  d_in[3];
    const float* edge_attr  = (const float*)d_in[4];
    const float* ele        = (const float*)d_in[5];
    const float* sc_w0      = (const float*)d_in[6];
    const float* sc_w1      = (const float*)d_in[7];
    const float* lin1_w0    = (const float*)d_in[8];
    const float* lin1_w1    = (const float*)d_in[9];
    const float* fc_w0      = (const float*)d_in[10];
    const float* fc_w1      = (const float*)d_in[11];
    const float* lin2_w0    = (const float*)d_in[12];
    const float* lin2_w1    = (const float*)d_in[13];
    const float* lin2_w2    = (const float*)d_in[14];
    float* out = (float*)d_out;

    static cudaStream_t s2 = nullptr;
    static cudaEvent_t evA = nullptr, evB = nullptr;
    if (s2 == nullptr) {
        cudaStreamCreateWithFlags(&s2, cudaStreamNonBlocking);
        cudaEventCreateWithFlags(&evA, cudaEventDisableTiming);
        cudaEventCreateWithFlags(&evB, cudaEventDisableTiming);
    }

    const int smem_out = 16 * 960 * 4;   // 60 KB
    cudaFuncSetAttribute(k_out, cudaFuncAttributeMaxDynamicSharedMemorySize, smem_out);

    // fork point at capture origin: gemm depends only on raw inputs
    cudaEventRecord(evA, 0);
    cudaStreamWaitEvent(s2, evA, 0);

    k_bucket<<<(NE + 255) / 256, 256>>>(edge_dst);                                   // idx 0
    k_node<<<NN / 16, 160>>>(node_input, node_attr, lin1_w0, sc_w0, lin1_w1, sc_w1); // idx 1
    k_gemm<<<NE / GE, 160, 0, s2>>>(ele, fc_w0, fc_w1);                              // idx 2 (concurrent)
    cudaEventRecord(evB, s2);
    cudaStreamWaitEvent(0, evB, 0);

    k_gather<<<NN, 320>>>(edge_attr, edge_src);                                      // idx 3 -> profiled
    k_out<<<NN / 16, 320, smem_out>>>(node_attr, lin2_w0, lin2_w1, lin2_w2, out);    // idx 4
}

// round 16
// speedup vs baseline: 1.3452x; 1.1243x over previous
#include <cuda_runtime.h>
#include <cstdint>

#define NN 10000
#define NE 160000
#define CAP 96
#define TE 8

#define SILU_C_F   1.6765867f
#define INV_S8     0.35355339059327373f
#define INV_S32    0.17677669529663687f
#define INV_S96    0.10206207261596575f
#define INV_S128   0.08838834764831845f
#define INV_S3     0.57735026918962576f
#define S3_DIV_S5  0.77459666924148338f   // sqrt(3/5)
#define IS2        0.70710678118654752f   // 1/sqrt(2)
#define IS6        0.40824829046386302f   // 1/sqrt(6)
#define C_S        0.38268343236508977f   // sin(pi/8)
#define C_X        0.92387953251128676f   // cos(pi/8)

// scratch
__device__ float g_y[NN * 160];
__device__ float g_s[NN * 160];       // self-connection, C_S pre-folded
__device__ float g_w[NE * 320];       // per-edge TP weights (GEMM output)
__device__ float g_agg[NN * 960];     // gathered accumulators [m(96)|m1T(384)|m2T(480)]
// sort scratch (compact CSR)
__device__ int g_count[NN];
__device__ int g_fill[NN];
__device__ int g_offset[NN + 1];
__device__ int g_perm[NE];

__device__ __forceinline__ unsigned long long pack2(float x) {
    unsigned long long r; asm("mov.b64 %0, {%1, %1};" : "=l"(r) : "f"(x)); return r;
}
__device__ __forceinline__ void fma2(unsigned long long& d, unsigned long long a, unsigned long long b) {
    asm("fma.rn.f32x2 %0, %1, %2, %0;" : "+l"(d) : "l"(a), "l"(b));
}
__device__ __forceinline__ float2 unpack2(unsigned long long v) {
    float2 f; asm("mov.b64 {%0, %1}, %2;" : "=f"(f.x), "=f"(f.y) : "l"(v)); return f;
}
__device__ __forceinline__ void cpa16(uint32_t s, const void* g) {
    asm volatile("cp.async.cg.shared.global [%0], [%1], 16;" :: "r"(s), "l"(g) : "memory");
}
#define CPA_COMMIT() asm volatile("cp.async.commit_group;" ::: "memory")
#define CPA_WAIT0()  asm volatile("cp.async.wait_group 0;" ::: "memory")
#define CPA_WAIT1()  asm volatile("cp.async.wait_group 1;" ::: "memory")

// ---------------- zero counters ----------------
__global__ void k_zero() {
    int i = blockIdx.x * blockDim.x + threadIdx.x;
    if (i < NN) { g_count[i] = 0; g_fill[i] = 0; }
}
// ---------------- histogram / scan / permutation ----------------
__global__ void k_hist(const int* __restrict__ edge_dst) {
    int i = blockIdx.x * blockDim.x + threadIdx.x;
    if (i < NE) atomicAdd(&g_count[edge_dst[i]], 1);
}
__global__ __launch_bounds__(512) void k_scan() {
    __shared__ int part[512];
    int t = threadIdx.x;
    int base = t * 20;
    int s = 0;
    #pragma unroll
    for (int i = 0; i < 20; i++) { int idx = base + i; if (idx < NN) s += g_count[idx]; }
    part[t] = s;
    __syncthreads();
    for (int d = 1; d < 512; d <<= 1) {
        int v = (t >= d) ? part[t - d] : 0;
        __syncthreads();
        part[t] += v;
        __syncthreads();
    }
    int run = (t > 0) ? part[t - 1] : 0;
    for (int i = 0; i < 20; i++) {
        int idx = base + i;
        if (idx < NN) { g_offset[idx] = run; run += g_count[idx]; }
    }
    if (t == 511) g_offset[NN] = run;
}
__global__ void k_fill(const int* __restrict__ edge_dst) {
    int e = blockIdx.x * blockDim.x + threadIdx.x;
    if (e < NE) {
        int d = edge_dst[e];
        int p = atomicAdd(&g_fill[d], 1);
        g_perm[g_offset[d] + p] = e;
    }
}

// ---------------- node pre-linear: 16-node tile, col-owner, coalesced weights ----------------
__global__ __launch_bounds__(160) void k_node(
    const float* __restrict__ node_input, const float* __restrict__ node_attr,
    const float* __restrict__ lin1_w0, const float* __restrict__ sc_w0,
    const float* __restrict__ lin1_w1, const float* __restrict__ sc_w1)
{
    __shared__ float xs[16][160];
    __shared__ float natt[16];
    int n0 = blockIdx.x * 16, t = threadIdx.x;
    for (int idx = t; idx < 16 * 160; idx += 160) {
        int nn = idx / 160, col = idx - nn * 160;
        xs[nn][col] = node_input[(n0 + nn) * 160 + col];
    }
    if (t < 16) natt[t] = node_attr[n0 + t];
    __syncthreads();

    float accy[16], accs[16];
    #pragma unroll
    for (int nn = 0; nn < 16; nn++) { accy[nn] = 0.f; accs[nn] = 0.f; }

    if (t < 64) {
        #pragma unroll 1
        for (int uc = 0; uc < 64; uc += 16) {
            float wl[16], ws[16];
            #pragma unroll
            for (int q = 0; q < 16; q++) {
                wl[q] = __ldg(&lin1_w0[(uc + q) * 64 + t]);
                ws[q] = __ldg(&sc_w0[(uc + q) * 64 + t]);
            }
            #pragma unroll
            for (int nn = 0; nn < 16; nn++) {
                #pragma unroll
                for (int q = 0; q < 16; q += 4) {
                    float4 xv = *reinterpret_cast<const float4*>(&xs[nn][uc + q]);
                    accy[nn] = fmaf(xv.x, wl[q], fmaf(xv.y, wl[q+1], fmaf(xv.z, wl[q+2], fmaf(xv.w, wl[q+3], accy[nn]))));
                    accs[nn] = fmaf(xv.x, ws[q], fmaf(xv.y, ws[q+1], fmaf(xv.z, ws[q+2], fmaf(xv.w, ws[q+3], accs[nn]))));
                }
            }
        }
        #pragma unroll
        for (int nn = 0; nn < 16; nn++) {
            float a = natt[nn];
            g_y[(n0 + nn) * 160 + t] = accy[nn] * a * 0.125f;
            g_s[(n0 + nn) * 160 + t] = accs[nn] * a * (0.125f * C_S);
        }
    } else {
        int j = t - 64, v = j / 3, i = j - 3 * v;
        #pragma unroll 1
        for (int uc = 0; uc < 32; uc += 16) {
            float wl[16], ws[16];
            #pragma unroll
            for (int q = 0; q < 16; q++) {
                wl[q] = __ldg(&lin1_w1[(uc + q) * 32 + v]);
                ws[q] = __ldg(&sc_w1[(uc + q) * 32 + v]);
            }
            #pragma unroll
            for (int nn = 0; nn < 16; nn++) {
                #pragma unroll
                for (int q = 0; q < 16; q++) {
                    float xv = xs[nn][64 + (uc + q) * 3 + i];
                    accy[nn] = fmaf(xv, wl[q], accy[nn]);
                    accs[nn] = fmaf(xv, ws[q], accs[nn]);
                }
            }
        }
        #pragma unroll
        for (int nn = 0; nn < 16; nn++) {
            float a = natt[nn];
            g_y[(n0 + nn) * 160 + t] = accy[nn] * a * INV_S32;
            g_s[(n0 + nn) * 160 + t] = accs[nn] * a * (INV_S32 * C_S);
        }
    }
}

// ---------------- GEMM: W[e][c] = h(e) . fc_w1[:,c]; 4 cols x 8 edges per thread ----------------
#define GE 16
__global__ __launch_bounds__(160) void k_gemm(
    const float* __restrict__ ele, const float* __restrict__ fc_w0,
    const float* __restrict__ fc_w1)
{
    __shared__ float s_el[GE * 8];
    __shared__ float s_w0[512];
    __shared__ float sHT[64 * GE];   // sHT[k*16 + e]
    int t = threadIdx.x;
    int eb = blockIdx.x * GE;

    if (t < GE * 8) s_el[t] = ele[eb * 8 + t];
    for (int i = t; i < 512; i += 160) s_w0[i] = fc_w0[i];
    __syncthreads();

    if (t < 128) {
        int c = t >> 1, e0h = (t & 1) * 8;
        #pragma unroll
        for (int j = 0; j < 8; j++) {
            int e = e0h + j;
            float z = 0.f;
            #pragma unroll
            for (int k = 0; k < 8; k++) z = fmaf(s_el[e * 8 + k], s_w0[k * 64 + c], z);
            z *= INV_S8;
            float sg = __fdividef(1.f, 1.f + __expf(-z));
            sHT[c * GE + e] = z * sg * (SILU_C_F * 0.03125f);
        }
    }
    __syncthreads();

    int cq = t % 80;
    int eq = t / 80;
    int c0 = cq * 4;
    int e0 = eq * 8;

    unsigned long long acc[4][4];
    #pragma unroll
    for (int j = 0; j < 4; j++)
        #pragma unroll
        for (int p = 0; p < 4; p++) acc[j][p] = 0ULL;

    #pragma unroll 4
    for (int k = 0; k < 64; k++) {
        float4 wv = __ldg(reinterpret_cast<const float4*>(&fc_w1[k * 320 + c0]));
        unsigned long long w0 = pack2(wv.x), w1 = pack2(wv.y), w2 = pack2(wv.z), w3 = pack2(wv.w);
        const ulonglong2* hp = reinterpret_cast<const ulonglong2*>(&sHT[k * GE + e0]);
        ulonglong2 ha = hp[0];
        ulonglong2 hb = hp[1];
        fma2(acc[0][0], ha.x, w0); fma2(acc[0][1], ha.y, w0); fma2(acc[0][2], hb.x, w0); fma2(acc[0][3], hb.y, w0);
        fma2(acc[1][0], ha.x, w1); fma2(acc[1][1], ha.y, w1); fma2(acc[1][2], hb.x, w1); fma2(acc[1][3], hb.y, w1);
        fma2(acc[2][0], ha.x, w2); fma2(acc[2][1], ha.y, w2); fma2(acc[2][2], hb.x, w2); fma2(acc[2][3], hb.y, w2);
        fma2(acc[3][0], ha.x, w3); fma2(acc[3][1], ha.y, w3); fma2(acc[3][2], hb.x, w3); fma2(acc[3][3], hb.y, w3);
    }

    #pragma unroll
    for (int p = 0; p < 4; p++) {
        float2 v0 = unpack2(acc[0][p]), v1 = unpack2(acc[1][p]);
        float2 v2 = unpack2(acc[2][p]), v3 = unpack2(acc[3][p]);
        float4 lo = make_float4(v0.x, v1.x, v2.x, v3.x);
        float4 hi = make_float4(v0.y, v1.y, v2.y, v3.y);
        *reinterpret_cast<float4*>(&g_w[(eb + e0 + 2 * p) * 320 + c0]) = lo;
        *reinterpret_cast<float4*>(&g_w[(eb + e0 + 2 * p + 1) * 320 + c0]) = hi;
    }
}

// ---------------- gather v6: compact CSR + double-buffered cp.async tiles ----------------
// thread t ownership (verified):
//   [0,64): k0  | [64,128): k2  | [128,192): k5 | [192,224): k3
//   [224,256): k1 | [256,288): k6 | [288,320): k4
__global__ __launch_bounds__(320) void k_gather(
    const float* __restrict__ edge_attr, const int* __restrict__ edge_src)
{
    __shared__ __align__(16) float sW[2][TE][320];   // 2 x 10 KB
    __shared__ __align__(16) float sY[2][TE][160];   // 2 x 5 KB
    __shared__ float mall[960];
    __shared__ float sea[CAP][16];                   // stride 16 -> shift/mask indexing
    __shared__ int sed[CAP];
    __shared__ int ssrc[CAP];
    float* m   = mall;
    float* m1T = mall + 96;
    float* m2T = mall + 480;

    int n = blockIdx.x, t = threadIdx.x;
    int off = g_offset[n];
    int deg = g_offset[n + 1] - off;
    if (deg > CAP) deg = CAP;   // Poisson(16): P(deg>96) astronomically small
    float acc0 = 0.f, acc1 = 0.f, acc2 = 0.f, acc3 = 0.f, acc4 = 0.f;

    int eabase;
    if      (t < 64)  eabase = 0;
    else if (t < 128) eabase = 1;
    else if (t < 192) eabase = 4;
    else if (t < 224) eabase = 0;
    else if (t < 288) eabase = 1;
    else              eabase = 4;

    if (t < deg) {
        int e = __ldg(&g_perm[off + t]);
        sed[t] = e;
        ssrc[t] = __ldg(&edge_src[e]);
    }
    __syncthreads();

    uint32_t sWb = (uint32_t)__cvta_generic_to_shared(&sW[0][0][0]);
    uint32_t sYb = (uint32_t)__cvta_generic_to_shared(&sY[0][0][0]);
    const uint32_t WBUF = TE * 320 * 4;   // 10240 B
    const uint32_t YBUF = TE * 160 * 4;   // 5120 B

    int ntiles = (deg + TE - 1) / TE;

    // issue tile 0 into buffer 0
    if (ntiles > 0) {
        int nt = deg < TE ? deg : TE;
        for (int idx = t; idx < nt * 128; idx += 320) {
            int j = idx >> 7, q = idx & 127;
            if (q < 80) {
                cpa16(sWb + (uint32_t)(j * 320 + q * 4) * 4,
                      &g_w[(size_t)sed[j] * 320 + q * 4]);
            } else if (q < 120) {
                int r = q - 80;
                cpa16(sYb + (uint32_t)(j * 160 + r * 4) * 4,
                      &g_y[(size_t)ssrc[j] * 160 + r * 4]);
            }
        }
    }
    CPA_COMMIT();

    // stage edge_attr (overlaps with cp.async in flight)
    for (int idx = t; idx < deg * 16; idx += 320) {
        int e = idx >> 4, j = idx & 15;
        if (j < 9) sea[e][j] = __ldg(&edge_attr[sed[e] * 9 + j]);
    }

    for (int tile = 0; tile < ntiles; tile++) {
        int buf = tile & 1;
        if (tile + 1 < ntiles) {
            int base = (tile + 1) * TE;
            int nt = deg - base; if (nt > TE) nt = TE;
            uint32_t wb = sWb + (buf ^ 1) * WBUF;
            uint32_t yb = sYb + (buf ^ 1) * YBUF;
            for (int idx = t; idx < nt * 128; idx += 320) {
                int j = idx >> 7, q = idx & 127;
                if (q < 80) {
                    cpa16(wb + (uint32_t)(j * 320 + q * 4) * 4,
                          &g_w[(size_t)sed[base + j] * 320 + q * 4]);
                } else if (q < 120) {
                    int r = q - 80;
                    cpa16(yb + (uint32_t)(j * 160 + r * 4) * 4,
                          &g_y[(size_t)ssrc[base + j] * 160 + r * 4]);
                }
            }
            CPA_COMMIT();
            CPA_WAIT1();
        } else {
            CPA_WAIT0();
        }
        __syncthreads();

        int base = tile * TE;
        int nt = deg - base; if (nt > TE) nt = TE;
        #pragma unroll 4
        for (int j = 0; j < nt; j++) {
            float w = sW[buf][j][t];
            float y0, y1 = 0.f, y2 = 0.f;
            if (t < 192) {
                y0 = sY[buf][j][t & 63];
            } else {
                int v3 = 64 + 3 * ((t - 192) & 31);
                y0 = sY[buf][j][v3]; y1 = sY[buf][j][v3 + 1]; y2 = sY[buf][j][v3 + 2];
            }
            const float* er = &sea[base + j][eabase];
            if (t < 64) {
                acc0 = fmaf(y0 * er[0], w, acc0);
            } else if (t < 128) {
                float b = y0 * w;
                acc0 = fmaf(b, er[0], acc0); acc1 = fmaf(b, er[1], acc1); acc2 = fmaf(b, er[2], acc2);
            } else if (t < 192) {
                float b = y0 * w;
                acc0 = fmaf(b, er[0], acc0); acc1 = fmaf(b, er[1], acc1); acc2 = fmaf(b, er[2], acc2);
                acc3 = fmaf(b, er[3], acc3); acc4 = fmaf(b, er[4], acc4);
            } else if (t < 224) {
                float b = er[0] * w;
                acc0 = fmaf(b, y0, acc0); acc1 = fmaf(b, y1, acc1); acc2 = fmaf(b, y2, acc2);
            } else if (t < 256) {
                acc0 = fmaf(INV_S3 * w, fmaf(y0, er[0], fmaf(y1, er[1], y2 * er[2])), acc0);
            } else if (t < 288) {
                float s = -w;
                acc0 = fmaf(s, (y2 * er[0] + y0 * er[2]) * IS2, acc0);
                acc1 = fmaf(s, (y0 * er[1] + y1 * er[0]) * IS2, acc1);
                acc2 = fmaf(s, (-y0 * er[0] + 2.f * y1 * er[1] - y2 * er[2]) * IS6, acc2);
                acc3 = fmaf(s, (y1 * er[2] + y2 * er[1]) * IS2, acc3);
                acc4 = fmaf(s, (-y0 * er[0] + y2 * er[2]) * IS2, acc4);
            } else {
                float p0 = er[0], p1 = er[1], p2 = er[2], p3 = er[3], p4 = er[4];
                float Myy = -p2 * IS6 - p4 * IS2;
                float Mzz =  2.f * p2 * IS6;
                float Mxx = -p2 * IS6 + p4 * IS2;
                float Myz =  p1 * IS2;
                float Myx =  p0 * IS2;
                float Mzx =  p3 * IS2;
                float s = S3_DIV_S5 * w;
                acc0 = fmaf(s, fmaf(Myy, y0, fmaf(Myz, y1, Myx * y2)), acc0);
                acc1 = fmaf(s, fmaf(Myz, y0, fmaf(Mzz, y1, Mzx * y2)), acc1);
                acc2 = fmaf(s, fmaf(Myx, y0, fmaf(Mzx, y1, Mxx * y2)), acc2);
            }
        }
        __syncthreads();   // buffer reuse fence
    }

    // stage accumulators into lin2-friendly smem layouts
    if (t < 64) {
        m[t] = acc0;
    } else if (t < 128) {
        int u = t - 64;
        m1T[u] = acc0; m1T[128 + u] = acc1; m1T[256 + u] = acc2;
    } else if (t < 192) {
        int u = t - 128;
        m2T[u] = acc0; m2T[96 + u] = acc1; m2T[192 + u] = acc2;
        m2T[288 + u] = acc3; m2T[384 + u] = acc4;
    } else if (t < 224) {
        int v = t - 192 + 64;
        m1T[v] = acc0; m1T[128 + v] = acc1; m1T[256 + v] = acc2;
    } else if (t < 256) {
        m[64 + (t - 224)] = acc0;
    } else if (t < 288) {
        int v = t - 256 + 64;
        m2T[v] = acc0; m2T[96 + v] = acc1; m2T[192 + v] = acc2;
        m2T[288 + v] = acc3; m2T[384 + v] = acc4;
    } else {
        int v = t - 288 + 96;
        m1T[v] = acc0; m1T[128 + v] = acc1; m1T[256 + v] = acc2;
    }
    __syncthreads();

    for (int idx = t; idx < 960; idx += 320)
        g_agg[n * 960 + idx] = mall[idx];
}

// ---------------- output: lin2 + combine; 16-node tile, col-owner, coalesced weights ----------------
__global__ __launch_bounds__(320) void k_out(
    const float* __restrict__ node_attr,
    const float* __restrict__ lin2_w0, const float* __restrict__ lin2_w1,
    const float* __restrict__ lin2_w2, float* __restrict__ out)
{
    extern __shared__ float sag[];   // [16][960]
    __shared__ float natt[16];
    int n0 = blockIdx.x * 16, t = threadIdx.x;
    for (int idx = t; idx < 16 * 960; idx += 320)
        sag[idx] = g_agg[n0 * 960 + idx];
    if (t < 16) natt[t] = node_attr[n0 + t];
    __syncthreads();

    float acc[16];
    #pragma unroll
    for (int nn = 0; nn < 16; nn++) acc[nn] = 0.f;

    if (t < 64) {
        #pragma unroll 1
        for (int pc = 0; pc < 96; pc += 16) {
            float w[16];
            #pragma unroll
            for (int q = 0; q < 16; q++) w[q] = __ldg(&lin2_w0[(pc + q) * 64 + t]);
            #pragma unroll
            for (int nn = 0; nn < 16; nn++) {
                const float* mp = &sag[nn * 960 + pc];
                #pragma unroll
                for (int q = 0; q < 16; q += 4) {
                    float4 mv = *reinterpret_cast<const float4*>(mp + q);
                    acc[nn] = fmaf(mv.x, w[q], fmaf(mv.y, w[q+1], fmaf(mv.z, w[q+2], fmaf(mv.w, w[q+3], acc[nn]))));
                }
            }
        }
        #pragma unroll
        for (int nn = 0; nn < 16; nn++) {
            int n = n0 + nn;
            out[n * 320 + t] = __ldg(&g_s[n * 160 + t]) + acc[nn] * natt[nn] * (C_X * INV_S96);
        }
    } else if (t < 160) {
        int j = t - 64, v = j / 3, i = j - 3 * v;
        #pragma unroll 1
        for (int pc = 0; pc < 128; pc += 16) {
            float w[16];
            #pragma unroll
            for (int q = 0; q < 16; q++) w[q] = __ldg(&lin2_w1[(pc + q) * 32 + v]);
            #pragma unroll
            for (int nn = 0; nn < 16; nn++) {
                const float* mp = &sag[nn * 960 + 96 + i * 128 + pc];
                #pragma unroll
                for (int q = 0; q < 16; q += 4) {
                    float4 mv = *reinterpret_cast<const float4*>(mp + q);
                    acc[nn] = fmaf(mv.x, w[q], fmaf(mv.y, w[q+1], fmaf(mv.z, w[q+2], fmaf(mv.w, w[q+3], acc[nn]))));
                }
            }
        }
        #pragma unroll
        for (int nn = 0; nn < 16; nn++) {
            int n = n0 + nn;
            out[n * 320 + t] = __ldg(&g_s[n * 160 + t]) + acc[nn] * natt[nn] * (C_X * INV_S128);
        }
    } else {
        int j = t - 160, v = j / 5, i = j - 5 * v;
        #pragma unroll 1
        for (int pc = 0; pc < 96; pc += 16) {
            float w[16];
            #pragma unroll
            for (int q = 0; q < 16; q++) w[q] = __ldg(&lin2_w2[(pc + q) * 32 + v]);
            #pragma unroll
            for (int nn = 0; nn < 16; nn++) {
                const float* mp = &sag[nn * 960 + 480 + i * 96 + pc];
                #pragma unroll
                for (int q = 0; q < 16; q += 4) {
                    float4 mv = *reinterpret_cast<const float4*>(mp + q);
                    acc[nn] = fmaf(mv.x, w[q], fmaf(mv.y, w[q+1], fmaf(mv.z, w[q+2], fmaf(mv.w, w[q+3], acc[nn]))));
                }
            }
        }
        #pragma unroll
        for (int nn = 0; nn < 16; nn++) {
            int n = n0 + nn;
            out[n * 320 + t] = acc[nn] * natt[nn] * INV_S96;
        }
    }
}

extern "C" void kernel_launch(void* const* d_in, const int* in_sizes, int n_in,
                              void* d_out, int out_size)
{
    const float* node_input = (const float*)d_in[0];
    const float* node_attr  = (const float*)d_in[1];
    const int*   edge_src   = (const int*)  d_in[2];
    const int*   edge_dst   = (const int*)  d_in[3];
    const float* edge_attr  = (const float*)d_in[4];
    const float* ele        = (const float*)d_in[5];
    const float* sc_w0      = (const float*)d_in[6];
    const float* sc_w1      = (const float*)d_in[7];
    const float* lin1_w0    = (const float*)d_in[8];
    const float* lin1_w1    = (const float*)d_in[9];
    const float* fc_w0      = (const float*)d_in[10];
    const float* fc_w1      = (const float*)d_in[11];
    const float* lin2_w0    = (const float*)d_in[12];
    const float* lin2_w1    = (const float*)d_in[13];
    const float* lin2_w2    = (const float*)d_in[14];
    float* out = (float*)d_out;

    static cudaStream_t s2 = nullptr;
    static cudaEvent_t evA = nullptr, evB = nullptr;
    if (s2 == nullptr) {
        cudaStreamCreateWithFlags(&s2, cudaStreamNonBlocking);
        cudaEventCreateWithFlags(&evA, cudaEventDisableTiming);
        cudaEventCreateWithFlags(&evB, cudaEventDisableTiming);
    }

    const int smem_out = 16 * 960 * 4;   // 60 KB
    cudaFuncSetAttribute(k_out, cudaFuncAttributeMaxDynamicSharedMemorySize, smem_out);

    // fork: gemm depends only on raw inputs -> concurrent with sort chain + node
    cudaEventRecord(evA, 0);
    cudaStreamWaitEvent(s2, evA, 0);
    k_gemm<<<NE / GE, 160, 0, s2>>>(ele, fc_w0, fc_w1);
    cudaEventRecord(evB, s2);

    k_zero<<<(NN + 255) / 256, 256>>>();
    k_hist<<<(NE + 255) / 256, 256>>>(edge_dst);
    k_scan<<<1, 512>>>();
    k_fill<<<(NE + 255) / 256, 256>>>(edge_dst);
    k_node<<<NN / 16, 160>>>(node_input, node_attr, lin1_w0, sc_w0, lin1_w1, sc_w1);

    cudaStreamWaitEvent(0, evB, 0);
    k_gather<<<NN, 320>>>(edge_attr, edge_src);
    k_out<<<NN / 16, 320, smem_out>>>(node_attr, lin2_w0, lin2_w1, lin2_w2, out);
}

// round 17
// speedup vs baseline: 1.3580x; 1.0095x over previous
#include <cuda_runtime.h>
#include <cuda_fp16.h>
#include <cstdint>

#define NN 10000
#define NE 160000
#define CAP 96
#define TE 16

#define SILU_C_F   1.6765867f
#define INV_S8     0.35355339059327373f
#define INV_S32    0.17677669529663687f
#define INV_S96    0.10206207261596575f
#define INV_S128   0.08838834764831845f
#define INV_S3     0.57735026918962576f
#define S3_DIV_S5  0.77459666924148338f   // sqrt(3/5)
#define IS2        0.70710678118654752f   // 1/sqrt(2)
#define IS6        0.40824829046386302f   // 1/sqrt(6)
#define C_S        0.38268343236508977f   // sin(pi/8)
#define C_X        0.92387953251128676f   // cos(pi/8)

// scratch
__device__ float  g_y[NN * 160];
__device__ float  g_s[NN * 160];      // self-connection, C_S pre-folded
__device__ __half g_w[NE * 320];      // per-edge TP weights, fp16 (halved stream)
__device__ float  g_agg[NN * 960];    // gathered accumulators [m(96)|m1T(384)|m2T(480)]
// sort scratch (compact CSR)
__device__ int g_count[NN];
__device__ int g_fill[NN];
__device__ int g_offset[NN + 1];
__device__ int g_perm[NE];

__device__ __forceinline__ unsigned long long pack2(float x) {
    unsigned long long r; asm("mov.b64 %0, {%1, %1};" : "=l"(r) : "f"(x)); return r;
}
__device__ __forceinline__ void fma2(unsigned long long& d, unsigned long long a, unsigned long long b) {
    asm("fma.rn.f32x2 %0, %1, %2, %0;" : "+l"(d) : "l"(a), "l"(b));
}
__device__ __forceinline__ float2 unpack2(unsigned long long v) {
    float2 f; asm("mov.b64 {%0, %1}, %2;" : "=f"(f.x), "=f"(f.y) : "l"(v)); return f;
}
__device__ __forceinline__ void cpa16(uint32_t s, const void* g) {
    asm volatile("cp.async.cg.shared.global [%0], [%1], 16;" :: "r"(s), "l"(g) : "memory");
}
#define CPA_COMMIT() asm volatile("cp.async.commit_group;" ::: "memory")
#define CPA_WAIT0()  asm volatile("cp.async.wait_group 0;" ::: "memory")
#define CPA_WAIT1()  asm volatile("cp.async.wait_group 1;" ::: "memory")

// ---------------- zero counters ----------------
__global__ void k_zero() {
    int i = blockIdx.x * blockDim.x + threadIdx.x;
    if (i < NN) { g_count[i] = 0; g_fill[i] = 0; }
}
// ---------------- histogram / scan / permutation ----------------
__global__ void k_hist(const int* __restrict__ edge_dst) {
    int i = blockIdx.x * blockDim.x + threadIdx.x;
    if (i < NE) atomicAdd(&g_count[edge_dst[i]], 1);
}
__global__ __launch_bounds__(512) void k_scan() {
    __shared__ int part[512];
    int t = threadIdx.x;
    int base = t * 20;
    int s = 0;
    #pragma unroll
    for (int i = 0; i < 20; i++) { int idx = base + i; if (idx < NN) s += g_count[idx]; }
    part[t] = s;
    __syncthreads();
    for (int d = 1; d < 512; d <<= 1) {
        int v = (t >= d) ? part[t - d] : 0;
        __syncthreads();
        part[t] += v;
        __syncthreads();
    }
    int run = (t > 0) ? part[t - 1] : 0;
    for (int i = 0; i < 20; i++) {
        int idx = base + i;
        if (idx < NN) { g_offset[idx] = run; run += g_count[idx]; }
    }
    if (t == 511) g_offset[NN] = run;
}
__global__ void k_fill(const int* __restrict__ edge_dst) {
    int e = blockIdx.x * blockDim.x + threadIdx.x;
    if (e < NE) {
        int d = edge_dst[e];
        int p = atomicAdd(&g_fill[d], 1);
        g_perm[g_offset[d] + p] = e;
    }
}

// ---------------- node pre-linear: 16-node tile, col-owner, coalesced weights ----------------
__global__ __launch_bounds__(160) void k_node(
    const float* __restrict__ node_input, const float* __restrict__ node_attr,
    const float* __restrict__ lin1_w0, const float* __restrict__ sc_w0,
    const float* __restrict__ lin1_w1, const float* __restrict__ sc_w1)
{
    __shared__ float xs[16][160];
    __shared__ float natt[16];
    int n0 = blockIdx.x * 16, t = threadIdx.x;
    for (int idx = t; idx < 16 * 160; idx += 160) {
        int nn = idx / 160, col = idx - nn * 160;
        xs[nn][col] = node_input[(n0 + nn) * 160 + col];
    }
    if (t < 16) natt[t] = node_attr[n0 + t];
    __syncthreads();

    float accy[16], accs[16];
    #pragma unroll
    for (int nn = 0; nn < 16; nn++) { accy[nn] = 0.f; accs[nn] = 0.f; }

    if (t < 64) {
        #pragma unroll 1
        for (int uc = 0; uc < 64; uc += 16) {
            float wl[16], ws[16];
            #pragma unroll
            for (int q = 0; q < 16; q++) {
                wl[q] = __ldg(&lin1_w0[(uc + q) * 64 + t]);
                ws[q] = __ldg(&sc_w0[(uc + q) * 64 + t]);
            }
            #pragma unroll
            for (int nn = 0; nn < 16; nn++) {
                #pragma unroll
                for (int q = 0; q < 16; q += 4) {
                    float4 xv = *reinterpret_cast<const float4*>(&xs[nn][uc + q]);
                    accy[nn] = fmaf(xv.x, wl[q], fmaf(xv.y, wl[q+1], fmaf(xv.z, wl[q+2], fmaf(xv.w, wl[q+3], accy[nn]))));
                    accs[nn] = fmaf(xv.x, ws[q], fmaf(xv.y, ws[q+1], fmaf(xv.z, ws[q+2], fmaf(xv.w, ws[q+3], accs[nn]))));
                }
            }
        }
        #pragma unroll
        for (int nn = 0; nn < 16; nn++) {
            float a = natt[nn];
            g_y[(n0 + nn) * 160 + t] = accy[nn] * a * 0.125f;
            g_s[(n0 + nn) * 160 + t] = accs[nn] * a * (0.125f * C_S);
        }
    } else {
        int j = t - 64, v = j / 3, i = j - 3 * v;
        #pragma unroll 1
        for (int uc = 0; uc < 32; uc += 16) {
            float wl[16], ws[16];
            #pragma unroll
            for (int q = 0; q < 16; q++) {
                wl[q] = __ldg(&lin1_w1[(uc + q) * 32 + v]);
                ws[q] = __ldg(&sc_w1[(uc + q) * 32 + v]);
            }
            #pragma unroll
            for (int nn = 0; nn < 16; nn++) {
                #pragma unroll
                for (int q = 0; q < 16; q++) {
                    float xv = xs[nn][64 + (uc + q) * 3 + i];
                    accy[nn] = fmaf(xv, wl[q], accy[nn]);
                    accs[nn] = fmaf(xv, ws[q], accs[nn]);
                }
            }
        }
        #pragma unroll
        for (int nn = 0; nn < 16; nn++) {
            float a = natt[nn];
            g_y[(n0 + nn) * 160 + t] = accy[nn] * a * INV_S32;
            g_s[(n0 + nn) * 160 + t] = accs[nn] * a * (INV_S32 * C_S);
        }
    }
}

// ---------------- GEMM: W[e][c] = h(e) . fc_w1[:,c]; fp16 output ----------------
#define GE 16
__global__ __launch_bounds__(160) void k_gemm(
    const float* __restrict__ ele, const float* __restrict__ fc_w0,
    const float* __restrict__ fc_w1)
{
    __shared__ float s_el[GE * 8];
    __shared__ float s_w0[512];
    __shared__ float sHT[64 * GE];   // sHT[k*16 + e]
    int t = threadIdx.x;
    int eb = blockIdx.x * GE;

    if (t < GE * 8) s_el[t] = ele[eb * 8 + t];
    for (int i = t; i < 512; i += 160) s_w0[i] = fc_w0[i];
    __syncthreads();

    if (t < 128) {
        int c = t >> 1, e0h = (t & 1) * 8;
        #pragma unroll
        for (int j = 0; j < 8; j++) {
            int e = e0h + j;
            float z = 0.f;
            #pragma unroll
            for (int k = 0; k < 8; k++) z = fmaf(s_el[e * 8 + k], s_w0[k * 64 + c], z);
            z *= INV_S8;
            float sg = __fdividef(1.f, 1.f + __expf(-z));
            sHT[c * GE + e] = z * sg * (SILU_C_F * 0.03125f);
        }
    }
    __syncthreads();

    int cq = t % 80;
    int eq = t / 80;
    int c0 = cq * 4;
    int e0 = eq * 8;

    unsigned long long acc[4][4];
    #pragma unroll
    for (int j = 0; j < 4; j++)
        #pragma unroll
        for (int p = 0; p < 4; p++) acc[j][p] = 0ULL;

    #pragma unroll 4
    for (int k = 0; k < 64; k++) {
        float4 wv = __ldg(reinterpret_cast<const float4*>(&fc_w1[k * 320 + c0]));
        unsigned long long w0 = pack2(wv.x), w1 = pack2(wv.y), w2 = pack2(wv.z), w3 = pack2(wv.w);
        const ulonglong2* hp = reinterpret_cast<const ulonglong2*>(&sHT[k * GE + e0]);
        ulonglong2 ha = hp[0];
        ulonglong2 hb = hp[1];
        fma2(acc[0][0], ha.x, w0); fma2(acc[0][1], ha.y, w0); fma2(acc[0][2], hb.x, w0); fma2(acc[0][3], hb.y, w0);
        fma2(acc[1][0], ha.x, w1); fma2(acc[1][1], ha.y, w1); fma2(acc[1][2], hb.x, w1); fma2(acc[1][3], hb.y, w1);
        fma2(acc[2][0], ha.x, w2); fma2(acc[2][1], ha.y, w2); fma2(acc[2][2], hb.x, w2); fma2(acc[2][3], hb.y, w2);
        fma2(acc[3][0], ha.x, w3); fma2(acc[3][1], ha.y, w3); fma2(acc[3][2], hb.x, w3); fma2(acc[3][3], hb.y, w3);
    }

    #pragma unroll
    for (int p = 0; p < 4; p++) {
        float2 v0 = unpack2(acc[0][p]), v1 = unpack2(acc[1][p]);
        float2 v2 = unpack2(acc[2][p]), v3 = unpack2(acc[3][p]);
        __half2 a01 = __floats2half2_rn(v0.x, v1.x);
        __half2 a23 = __floats2half2_rn(v2.x, v3.x);
        __half2 b01 = __floats2half2_rn(v0.y, v1.y);
        __half2 b23 = __floats2half2_rn(v2.y, v3.y);
        uint2 pa, pb;
        pa.x = *reinterpret_cast<uint32_t*>(&a01); pa.y = *reinterpret_cast<uint32_t*>(&a23);
        pb.x = *reinterpret_cast<uint32_t*>(&b01); pb.y = *reinterpret_cast<uint32_t*>(&b23);
        *reinterpret_cast<uint2*>(&g_w[(size_t)(eb + e0 + 2 * p) * 320 + c0]) = pa;
        *reinterpret_cast<uint2*>(&g_w[(size_t)(eb + e0 + 2 * p + 1) * 320 + c0]) = pb;
    }
}

// ---------------- gather v7: fp16 W, TE=16 double-buffered cp.async tiles ----------------
// thread t ownership (verified):
//   [0,64): k0  | [64,128): k2  | [128,192): k5 | [192,224): k3
//   [224,256): k1 | [256,288): k6 | [288,320): k4
__global__ __launch_bounds__(320) void k_gather(
    const float* __restrict__ edge_attr, const int* __restrict__ edge_src)
{
    __shared__ __align__(16) __half sW[2][TE][320];   // 2 x 10 KB
    __shared__ __align__(16) float  sY[2][TE][160];   // 2 x 10 KB
    __shared__ float mall[960];
    __shared__ float sea[CAP][16];
    __shared__ int sed[CAP];
    __shared__ int ssrc[CAP];
    float* m   = mall;
    float* m1T = mall + 96;
    float* m2T = mall + 480;

    int n = blockIdx.x, t = threadIdx.x;
    int off = g_offset[n];
    int deg = g_offset[n + 1] - off;
    if (deg > CAP) deg = CAP;
    float acc0 = 0.f, acc1 = 0.f, acc2 = 0.f, acc3 = 0.f, acc4 = 0.f;

    int eabase;
    if      (t < 64)  eabase = 0;
    else if (t < 128) eabase = 1;
    else if (t < 192) eabase = 4;
    else if (t < 224) eabase = 0;
    else if (t < 288) eabase = 1;
    else              eabase = 4;

    if (t < deg) {
        int e = __ldg(&g_perm[off + t]);
        sed[t] = e;
        ssrc[t] = __ldg(&edge_src[e]);
    }
    __syncthreads();

    uint32_t sWb = (uint32_t)__cvta_generic_to_shared(&sW[0][0][0]);
    uint32_t sYb = (uint32_t)__cvta_generic_to_shared(&sY[0][0][0]);
    const uint32_t WBUF = TE * 320 * 2;   // 10240 B
    const uint32_t YBUF = TE * 160 * 4;   // 10240 B

    int ntiles = (deg + TE - 1) / TE;

    // issue tile 0 into buffer 0 (W: 40 x 16B halves-chunks, y: 40 x 16B float-chunks)
    if (ntiles > 0) {
        int nt = deg < TE ? deg : TE;
        for (int idx = t; idx < nt * 80; idx += 320) {
            int j = idx / 80, q = idx - j * 80;
            if (q < 40) {
                cpa16(sWb + (uint32_t)(j * 320 + q * 8) * 2,
                      &g_w[(size_t)sed[j] * 320 + q * 8]);
            } else {
                int r = q - 40;
                cpa16(sYb + (uint32_t)(j * 160 + r * 4) * 4,
                      &g_y[(size_t)ssrc[j] * 160 + r * 4]);
            }
        }
    }
    CPA_COMMIT();

    // stage edge_attr (overlaps with cp.async in flight)
    for (int idx = t; idx < deg * 16; idx += 320) {
        int e = idx >> 4, j = idx & 15;
        if (j < 9) sea[e][j] = __ldg(&edge_attr[sed[e] * 9 + j]);
    }

    for (int tile = 0; tile < ntiles; tile++) {
        int buf = tile & 1;
        if (tile + 1 < ntiles) {
            int base = (tile + 1) * TE;
            int nt = deg - base; if (nt > TE) nt = TE;
            uint32_t wb = sWb + (buf ^ 1) * WBUF;
            uint32_t yb = sYb + (buf ^ 1) * YBUF;
            for (int idx = t; idx < nt * 80; idx += 320) {
                int j = idx / 80, q = idx - j * 80;
                if (q < 40) {
                    cpa16(wb + (uint32_t)(j * 320 + q * 8) * 2,
                          &g_w[(size_t)sed[base + j] * 320 + q * 8]);
                } else {
                    int r = q - 40;
                    cpa16(yb + (uint32_t)(j * 160 + r * 4) * 4,
                          &g_y[(size_t)ssrc[base + j] * 160 + r * 4]);
                }
            }
            CPA_COMMIT();
            CPA_WAIT1();
        } else {
            CPA_WAIT0();
        }
        __syncthreads();

        int base = tile * TE;
        int nt = deg - base; if (nt > TE) nt = TE;
        #pragma unroll 4
        for (int j = 0; j < nt; j++) {
            float w = __half2float(sW[buf][j][t]);
            float y0, y1 = 0.f, y2 = 0.f;
            if (t < 192) {
                y0 = sY[buf][j][t & 63];
            } else {
                int v3 = 64 + 3 * ((t - 192) & 31);
                y0 = sY[buf][j][v3]; y1 = sY[buf][j][v3 + 1]; y2 = sY[buf][j][v3 + 2];
            }
            const float* er = &sea[base + j][eabase];
            if (t < 64) {
                acc0 = fmaf(y0 * er[0], w, acc0);
            } else if (t < 128) {
                float b = y0 * w;
                acc0 = fmaf(b, er[0], acc0); acc1 = fmaf(b, er[1], acc1); acc2 = fmaf(b, er[2], acc2);
            } else if (t < 192) {
                float b = y0 * w;
                acc0 = fmaf(b, er[0], acc0); acc1 = fmaf(b, er[1], acc1); acc2 = fmaf(b, er[2], acc2);
                acc3 = fmaf(b, er[3], acc3); acc4 = fmaf(b, er[4], acc4);
            } else if (t < 224) {
                float b = er[0] * w;
                acc0 = fmaf(b, y0, acc0); acc1 = fmaf(b, y1, acc1); acc2 = fmaf(b, y2, acc2);
            } else if (t < 256) {
                acc0 = fmaf(INV_S3 * w, fmaf(y0, er[0], fmaf(y1, er[1], y2 * er[2])), acc0);
            } else if (t < 288) {
                float s = -w;
                acc0 = fmaf(s, (y2 * er[0] + y0 * er[2]) * IS2, acc0);
                acc1 = fmaf(s, (y0 * er[1] + y1 * er[0]) * IS2, acc1);
                acc2 = fmaf(s, (-y0 * er[0] + 2.f * y1 * er[1] - y2 * er[2]) * IS6, acc2);
                acc3 = fmaf(s, (y1 * er[2] + y2 * er[1]) * IS2, acc3);
                acc4 = fmaf(s, (-y0 * er[0] + y2 * er[2]) * IS2, acc4);
            } else {
                float p0 = er[0], p1 = er[1], p2 = er[2], p3 = er[3], p4 = er[4];
                float Myy = -p2 * IS6 - p4 * IS2;
                float Mzz =  2.f * p2 * IS6;
                float Mxx = -p2 * IS6 + p4 * IS2;
                float Myz =  p1 * IS2;
                float Myx =  p0 * IS2;
                float Mzx =  p3 * IS2;
                float s = S3_DIV_S5 * w;
                acc0 = fmaf(s, fmaf(Myy, y0, fmaf(Myz, y1, Myx * y2)), acc0);
                acc1 = fmaf(s, fmaf(Myz, y0, fmaf(Mzz, y1, Mzx * y2)), acc1);
                acc2 = fmaf(s, fmaf(Myx, y0, fmaf(Mzx, y1, Mxx * y2)), acc2);
            }
        }
        __syncthreads();   // buffer reuse fence
    }

    // stage accumulators into lin2-friendly smem layouts
    if (t < 64) {
        m[t] = acc0;
    } else if (t < 128) {
        int u = t - 64;
        m1T[u] = acc0; m1T[128 + u] = acc1; m1T[256 + u] = acc2;
    } else if (t < 192) {
        int u = t - 128;
        m2T[u] = acc0; m2T[96 + u] = acc1; m2T[192 + u] = acc2;
        m2T[288 + u] = acc3; m2T[384 + u] = acc4;
    } else if (t < 224) {
        int v = t - 192 + 64;
        m1T[v] = acc0; m1T[128 + v] = acc1; m1T[256 + v] = acc2;
    } else if (t < 256) {
        m[64 + (t - 224)] = acc0;
    } else if (t < 288) {
        int v = t - 256 + 64;
        m2T[v] = acc0; m2T[96 + v] = acc1; m2T[192 + v] = acc2;
        m2T[288 + v] = acc3; m2T[384 + v] = acc4;
    } else {
        int v = t - 288 + 96;
        m1T[v] = acc0; m1T[128 + v] = acc1; m1T[256 + v] = acc2;
    }
    __syncthreads();

    for (int idx = t; idx < 960; idx += 320)
        g_agg[n * 960 + idx] = mall[idx];
}

// ---------------- output: lin2 + combine; 16-node tile, col-owner, coalesced weights ----------------
__global__ __launch_bounds__(320) void k_out(
    const float* __restrict__ node_attr,
    const float* __restrict__ lin2_w0, const float* __restrict__ lin2_w1,
    const float* __restrict__ lin2_w2, float* __restrict__ out)
{
    extern __shared__ float sag[];   // [16][960]
    __shared__ float natt[16];
    int n0 = blockIdx.x * 16, t = threadIdx.x;
    for (int idx = t; idx < 16 * 960; idx += 320)
        sag[idx] = g_agg[n0 * 960 + idx];
    if (t < 16) natt[t] = node_attr[n0 + t];
    __syncthreads();

    float acc[16];
    #pragma unroll
    for (int nn = 0; nn < 16; nn++) acc[nn] = 0.f;

    if (t < 64) {
        #pragma unroll 1
        for (int pc = 0; pc < 96; pc += 16) {
            float w[16];
            #pragma unroll
            for (int q = 0; q < 16; q++) w[q] = __ldg(&lin2_w0[(pc + q) * 64 + t]);
            #pragma unroll
            for (int nn = 0; nn < 16; nn++) {
                const float* mp = &sag[nn * 960 + pc];
                #pragma unroll
                for (int q = 0; q < 16; q += 4) {
                    float4 mv = *reinterpret_cast<const float4*>(mp + q);
                    acc[nn] = fmaf(mv.x, w[q], fmaf(mv.y, w[q+1], fmaf(mv.z, w[q+2], fmaf(mv.w, w[q+3], acc[nn]))));
                }
            }
        }
        #pragma unroll
        for (int nn = 0; nn < 16; nn++) {
            int n = n0 + nn;
            out[n * 320 + t] = __ldg(&g_s[n * 160 + t]) + acc[nn] * natt[nn] * (C_X * INV_S96);
        }
    } else if (t < 160) {
        int j = t - 64, v = j / 3, i = j - 3 * v;
        #pragma unroll 1
        for (int pc = 0; pc < 128; pc += 16) {
            float w[16];
            #pragma unroll
            for (int q = 0; q < 16; q++) w[q] = __ldg(&lin2_w1[(pc + q) * 32 + v]);
            #pragma unroll
            for (int nn = 0; nn < 16; nn++) {
                const float* mp = &sag[nn * 960 + 96 + i * 128 + pc];
                #pragma unroll
                for (int q = 0; q < 16; q += 4) {
                    float4 mv = *reinterpret_cast<const float4*>(mp + q);
                    acc[nn] = fmaf(mv.x, w[q], fmaf(mv.y, w[q+1], fmaf(mv.z, w[q+2], fmaf(mv.w, w[q+3], acc[nn]))));
                }
            }
        }
        #pragma unroll
        for (int nn = 0; nn < 16; nn++) {
            int n = n0 + nn;
            out[n * 320 + t] = __ldg(&g_s[n * 160 + t]) + acc[nn] * natt[nn] * (C_X * INV_S128);
        }
    } else {
        int j = t - 160, v = j / 5, i = j - 5 * v;
        #pragma unroll 1
        for (int pc = 0; pc < 96; pc += 16) {
            float w[16];
            #pragma unroll
            for (int q = 0; q < 16; q++) w[q] = __ldg(&lin2_w2[(pc + q) * 32 + v]);
            #pragma unroll
            for (int nn = 0; nn < 16; nn++) {
                const float* mp = &sag[nn * 960 + 480 + i * 96 + pc];
                #pragma unroll
                for (int q = 0; q < 16; q += 4) {
                    float4 mv = *reinterpret_cast<const float4*>(mp + q);
                    acc[nn] = fmaf(mv.x, w[q], fmaf(mv.y, w[q+1], fmaf(mv.z, w[q+2], fmaf(mv.w, w[q+3], acc[nn]))));
                }
            }
        }
        #pragma unroll
        for (int nn = 0; nn < 16; nn++) {
            int n = n0 + nn;
            out[n * 320 + t] = acc[nn] * natt[nn] * INV_S96;
        }
    }
}

extern "C" void kernel_launch(void* const* d_in, const int* in_sizes, int n_in,
                              void* d_out, int out_size)
{
    const float* node_input = (const float*)d_in[0];
    const float* node_attr  = (const float*)d_in[1];
    const int*   edge_src   = (const int*)  d_in[2];
    const int*   edge_dst   = (const int*)  d_in[3];
    const float* edge_attr  = (const float*)d_in[4];
    const float* ele        = (const float*)d_in[5];
    const float* sc_w0      = (const float*)d_in[6];
    const float* sc_w1      = (const float*)d_in[7];
    const float* lin1_w0    = (const float*)d_in[8];
    const float* lin1_w1    = (const float*)d_in[9];
    const float* fc_w0      = (const float*)d_in[10];
    const float* fc_w1      = (const float*)d_in[11];
    const float* lin2_w0    = (const float*)d_in[12];
    const float* lin2_w1    = (const float*)d_in[13];
    const float* lin2_w2    = (const float*)d_in[14];
    float* out = (float*)d_out;

    static cudaStream_t s2 = nullptr;
    static cudaEvent_t evA = nullptr, evB = nullptr;
    if (s2 == nullptr) {
        cudaStreamCreateWithFlags(&s2, cudaStreamNonBlocking);
        cudaEventCreateWithFlags(&evA, cudaEventDisableTiming);
        cudaEventCreateWithFlags(&evB, cudaEventDisableTiming);
    }

    const int smem_out = 16 * 960 * 4;   // 60 KB
    cudaFuncSetAttribute(k_out, cudaFuncAttributeMaxDynamicSharedMemorySize, smem_out);

    // fork: gemm depends only on raw inputs -> concurrent with sort chain + node
    cudaEventRecord(evA, 0);
    cudaStreamWaitEvent(s2, evA, 0);
    k_gemm<<<NE / GE, 160, 0, s2>>>(ele, fc_w0, fc_w1);
    cudaEventRecord(evB, s2);

    k_zero<<<(NN + 255) / 256, 256>>>();
    k_hist<<<(NE + 255) / 256, 256>>>(edge_dst);
    k_scan<<<1, 512>>>();
    k_fill<<<(NE + 255) / 256, 256>>>(edge_dst);
    k_node<<<NN / 16, 160>>>(node_input, node_attr, lin1_w0, sc_w0, lin1_w1, sc_w1);

    cudaStreamWaitEvent(0, evB, 0);
    k_gather<<<NN, 320>>>(edge_attr, edge_src);
    k_out<<<NN / 16, 320, smem_out>>>(node_attr, lin2_w0, lin2_w1, lin2_w2, out);
}